// round 4
// baseline (speedup 1.0000x reference)
#include <cuda_runtime.h>
#include <cuda_bf16.h>
#include <mma.h>
#include <cstdint>

using namespace nvcuda;

#define N_IN   256
#define N_H    128
#define MAX_NODES 100000
#define MAX_EDGES 800000

// ---------------- scratch (allocation-free: __device__ globals) ----------------
// g_H has 128 pad rows so partial GEMM tiles can store unguarded.
__device__ float g_H[(2u * MAX_NODES + 128) * N_H];     // features [2N, 128] (+pad)
__device__ __nv_bfloat16 g_Wh[N_IN * N_H];              // W split hi (bf16)
__device__ __nv_bfloat16 g_Wl[N_IN * N_H];              // W split lo (bf16)
__device__ float g_wsum[N_H];                           // rowsum of lin_W
__device__ float g_bsum;                                // sum of lin_b
// CSR scratch (g_deg is zero at t=0 by static init and re-zeroed each run by scan_add)
__device__ int   g_deg[MAX_NODES + 1];
__device__ int   g_rowptr[MAX_NODES + 1];
__device__ int   g_fill[MAX_NODES];
__device__ int   g_blk[128];
__device__ int   g_ecol[MAX_EDGES];
__device__ float g_ewt[MAX_EDGES];

// =======================================================================
//  CSR construction
// =======================================================================
__global__ void hist_kernel(const int* __restrict__ ei, int n_edges)
{
    int i = blockIdx.x * blockDim.x + threadIdx.x;
    if (i < n_edges) atomicAdd(&g_deg[__ldg(ei + i)], 1);
}

// block-wise exclusive scan (1024 threads/block)
__global__ __launch_bounds__(1024) void scan_partial_kernel(int n, int n1)
{
    int tid  = threadIdx.x;
    int gid  = blockIdx.x * 1024 + tid;
    int lane = tid & 31, wid = tid >> 5;
    int v = (gid < n) ? g_deg[gid] : 0;
    int inc = v;
    #pragma unroll
    for (int o = 1; o < 32; o <<= 1) {
        int t = __shfl_up_sync(0xffffffffu, inc, o);
        if (lane >= o) inc += t;
    }
    __shared__ int ws[32];
    if (lane == 31) ws[wid] = inc;
    __syncthreads();
    if (wid == 0) {
        int s = ws[lane];
        #pragma unroll
        for (int o = 1; o < 32; o <<= 1) {
            int t = __shfl_up_sync(0xffffffffu, s, o);
            if (lane >= o) s += t;
        }
        ws[lane] = s;
    }
    __syncthreads();
    int woff = wid ? ws[wid - 1] : 0;
    int excl = woff + inc - v;
    if (gid < n1) g_rowptr[gid] = excl;
    if (tid == 1023) g_blk[blockIdx.x] = woff + inc;
}

// parallel exclusive scan of up to 128 block sums (one block, 128 threads)
__global__ __launch_bounds__(128) void scan_blk_kernel(int nb)
{
    int tid = threadIdx.x, lane = tid & 31, wid = tid >> 5;
    int v = (tid < nb) ? g_blk[tid] : 0;
    int inc = v;
    #pragma unroll
    for (int o = 1; o < 32; o <<= 1) {
        int t = __shfl_up_sync(0xffffffffu, inc, o);
        if (lane >= o) inc += t;
    }
    __shared__ int ws[4];
    if (lane == 31) ws[wid] = inc;
    __syncthreads();
    int carry = 0;
    #pragma unroll
    for (int w = 0; w < 4; w++) { if (w < wid) carry += ws[w]; }
    if (tid < nb) g_blk[tid] = carry + inc - v;   // exclusive
}

// add block offsets, publish g_fill, and re-zero g_deg for the next replay
__global__ __launch_bounds__(1024) void scan_add_kernel(int n, int n1)
{
    int gid = blockIdx.x * 1024 + threadIdx.x;
    if (gid < n1) {
        int r = g_rowptr[gid] + g_blk[blockIdx.x];
        g_rowptr[gid] = r;
        if (gid < n) g_fill[gid] = r;
        g_deg[gid] = 0;
    }
}

__global__ void scatter_kernel(const int* __restrict__ ei, const float* __restrict__ ew,
                               int n_edges)
{
    int i = blockIdx.x * blockDim.x + threadIdx.x;
    if (i >= n_edges) return;
    int   r = __ldg(ei + i);
    int   c = __ldg(ei + n_edges + i);
    float w = __ldg(ew + i);
    int p = atomicAdd(&g_fill[r], 1);
    g_ecol[p] = c;
    g_ewt[p]  = w;
}

// =======================================================================
//  prep (block 0): wsum / bsum;  all blocks: W bf16 split
//  grid = 128 blocks x 256 threads; wsplit handles 1 elem/thread.
// =======================================================================
__global__ __launch_bounds__(256) void prep_kernel(
    const float* __restrict__ linW, const float* __restrict__ linb,
    const float* __restrict__ W)
{
    // W split: 128 blocks * 256 threads = 32768 = N_IN*N_H
    int gi = blockIdx.x * 256 + threadIdx.x;
    {
        float v = __ldg(W + gi);
        __nv_bfloat16 h = __float2bfloat16(v);
        __nv_bfloat16 l = __float2bfloat16(v - __bfloat162float(h));
        g_Wh[gi] = h;
        g_Wl[gi] = l;
    }
    if (blockIdx.x != 0) return;

    int tid  = threadIdx.x;
    int warp = tid >> 5, lane = tid & 31;
    for (int k = warp; k < N_H; k += 8) {
        float s = 0.f;
        #pragma unroll
        for (int j = lane; j < N_H; j += 32) s += linW[k * N_H + j];
        #pragma unroll
        for (int o = 16; o > 0; o >>= 1) s += __shfl_down_sync(0xffffffffu, s, o);
        if (lane == 0) g_wsum[k] = s;
    }
    __shared__ float sb[256];
    sb[tid] = (tid < N_H) ? linb[tid] : 0.f;
    __syncthreads();
    for (int o = 128; o > 0; o >>= 1) { if (tid < o) sb[tid] += sb[tid + o]; __syncthreads(); }
    if (tid == 0) g_bsum = sb[0];
}

// =======================================================================
//  GEMM (one feature set): g_H[hbase + m] = x @ W  via wmma bf16 (3-term)
//  Tile 128x128, K=256 in 4 chunks of 64. 256 threads = 8 warps (2x4).
// =======================================================================
#define A_LD 72   // padded leading dim for smem A (bf16 elements)

__global__ __launch_bounds__(256) void gemm_wmma_kernel(
    const float* __restrict__ x, int n_rows, int hbase)
{
    __shared__ __nv_bfloat16 Ah[128][A_LD];
    __shared__ __nv_bfloat16 Al[128][A_LD];

    const int tid = threadIdx.x;
    const int wid = tid >> 5;
    const int warp_m = wid & 1;       // 0..1 -> 64 rows each
    const int warp_n = wid >> 1;      // 0..3 -> 32 cols each
    const int blockRow = blockIdx.x * 128;

    wmma::fragment<wmma::accumulator, 16, 16, 16, float> acc[4][2];
    #pragma unroll
    for (int mi = 0; mi < 4; mi++)
        #pragma unroll
        for (int ni = 0; ni < 2; ni++)
            wmma::fill_fragment(acc[mi][ni], 0.f);

    for (int ch = 0; ch < 4; ch++) {
        const int k0 = ch * 64;
        // ---- stage A chunk [128 x 64], split into bf16 hi/lo ----
        #pragma unroll
        for (int t = 0; t < 8; t++) {
            int e   = t * 256 + tid;           // 0..2047 float4 slots
            int row = e >> 4;                  // 0..127
            int c4  = e & 15;                  // 0..15
            int mg  = blockRow + row;
            float4 v = make_float4(0.f, 0.f, 0.f, 0.f);
            if (mg < n_rows)
                v = *reinterpret_cast<const float4*>(x + (size_t)mg * N_IN + k0 + c4 * 4);
            __nv_bfloat16 h0 = __float2bfloat16(v.x), l0 = __float2bfloat16(v.x - __bfloat162float(h0));
            __nv_bfloat16 h1 = __float2bfloat16(v.y), l1 = __float2bfloat16(v.y - __bfloat162float(h1));
            __nv_bfloat16 h2 = __float2bfloat16(v.z), l2 = __float2bfloat16(v.z - __bfloat162float(h2));
            __nv_bfloat16 h3 = __float2bfloat16(v.w), l3 = __float2bfloat16(v.w - __bfloat162float(h3));
            __nv_bfloat16* ph = &Ah[row][c4 * 4];
            __nv_bfloat16* pl = &Al[row][c4 * 4];
            ph[0] = h0; ph[1] = h1; ph[2] = h2; ph[3] = h3;
            pl[0] = l0; pl[1] = l1; pl[2] = l2; pl[3] = l3;
        }
        __syncthreads();

        // ---- MMA over 4 k-steps of 16 ----
        #pragma unroll
        for (int ks = 0; ks < 4; ks++) {
            const int kk = ks * 16;
            wmma::fragment<wmma::matrix_a, 16, 16, 16, __nv_bfloat16, wmma::row_major> ah[4], al[4];
            #pragma unroll
            for (int mi = 0; mi < 4; mi++) {
                int r0 = warp_m * 64 + mi * 16;
                wmma::load_matrix_sync(ah[mi], &Ah[r0][kk], A_LD);
                wmma::load_matrix_sync(al[mi], &Al[r0][kk], A_LD);
            }
            #pragma unroll
            for (int ni = 0; ni < 2; ni++) {
                int c0 = warp_n * 32 + ni * 16;
                wmma::fragment<wmma::matrix_b, 16, 16, 16, __nv_bfloat16, wmma::row_major> bh, bl;
                wmma::load_matrix_sync(bh, g_Wh + (size_t)(k0 + kk) * N_H + c0, N_H);
                wmma::load_matrix_sync(bl, g_Wl + (size_t)(k0 + kk) * N_H + c0, N_H);
                #pragma unroll
                for (int mi = 0; mi < 4; mi++) {
                    wmma::mma_sync(acc[mi][ni], ah[mi], bh, acc[mi][ni]);
                    wmma::mma_sync(acc[mi][ni], ah[mi], bl, acc[mi][ni]);
                    wmma::mma_sync(acc[mi][ni], al[mi], bh, acc[mi][ni]);
                }
            }
        }
        __syncthreads();
    }

    // ---- epilogue: store to g_H (pad rows / next-pass region absorb overflow,
    //      which is rewritten before being read) ----
    #pragma unroll
    for (int mi = 0; mi < 4; mi++) {
        int r0 = hbase + blockRow + warp_m * 64 + mi * 16;
        #pragma unroll
        for (int ni = 0; ni < 2; ni++) {
            int c0 = warp_n * 32 + ni * 16;
            wmma::store_matrix_sync(g_H + (size_t)r0 * N_H + c0, acc[mi][ni],
                                    N_H, wmma::mem_row_major);
        }
    }
}

// =======================================================================
//  Fused gather-SpMM + epilogue, ONE pass: warp per row
//  out[row + hbase] = dot(prelu(sum_e w_e H[hbase + c_e] + bias), wsum) + bsum
// =======================================================================
__global__ __launch_bounds__(256) void gather_pass_kernel(
    const float* __restrict__ bias, const float* __restrict__ pa,
    float* __restrict__ out, int n_nodes, int hbase)
{
    int row  = (blockIdx.x * blockDim.x + threadIdx.x) >> 5;
    int lane = threadIdx.x & 31;
    if (row >= n_nodes) return;

    int s = __ldg(&g_rowptr[row]);
    int e = __ldg(&g_rowptr[row + 1]);

    const float* Hb = g_H + (size_t)hbase * N_H;
    float4 a1 = make_float4(0.f, 0.f, 0.f, 0.f);

    int j = s;
    for (; j + 3 < e; j += 4) {
        int   c0 = __ldg(&g_ecol[j]),     c1 = __ldg(&g_ecol[j + 1]);
        int   c2 = __ldg(&g_ecol[j + 2]), c3 = __ldg(&g_ecol[j + 3]);
        float w0 = __ldg(&g_ewt[j]),      w1 = __ldg(&g_ewt[j + 1]);
        float w2 = __ldg(&g_ewt[j + 2]),  w3 = __ldg(&g_ewt[j + 3]);
        float4 u0 = reinterpret_cast<const float4*>(Hb + (size_t)c0 * N_H)[lane];
        float4 u1 = reinterpret_cast<const float4*>(Hb + (size_t)c1 * N_H)[lane];
        float4 u2 = reinterpret_cast<const float4*>(Hb + (size_t)c2 * N_H)[lane];
        float4 u3 = reinterpret_cast<const float4*>(Hb + (size_t)c3 * N_H)[lane];
        a1.x += w0 * u0.x + w1 * u1.x + w2 * u2.x + w3 * u3.x;
        a1.y += w0 * u0.y + w1 * u1.y + w2 * u2.y + w3 * u3.y;
        a1.z += w0 * u0.z + w1 * u1.z + w2 * u2.z + w3 * u3.z;
        a1.w += w0 * u0.w + w1 * u1.w + w2 * u2.w + w3 * u3.w;
    }
    for (; j < e; j++) {
        int   c0 = __ldg(&g_ecol[j]);
        float w0 = __ldg(&g_ewt[j]);
        float4 u0 = reinterpret_cast<const float4*>(Hb + (size_t)c0 * N_H)[lane];
        a1.x += w0 * u0.x;  a1.y += w0 * u0.y;  a1.z += w0 * u0.z;  a1.w += w0 * u0.w;
    }

    float  a = __ldg(pa);
    float4 b = __ldg(reinterpret_cast<const float4*>(bias) + lane);
    float4 w = *reinterpret_cast<const float4*>(g_wsum + lane * 4);

    float s1 = 0.f, t;
    t = a1.x + b.x; t = (t >= 0.f) ? t : a * t; s1 += t * w.x;
    t = a1.y + b.y; t = (t >= 0.f) ? t : a * t; s1 += t * w.y;
    t = a1.z + b.z; t = (t >= 0.f) ? t : a * t; s1 += t * w.z;
    t = a1.w + b.w; t = (t >= 0.f) ? t : a * t; s1 += t * w.w;

    #pragma unroll
    for (int o = 16; o > 0; o >>= 1) s1 += __shfl_down_sync(0xffffffffu, s1, o);
    if (lane == 0) out[row + hbase] = s1 + g_bsum;
}

// =======================================================================
//  launcher
// =======================================================================
extern "C" void kernel_launch(void* const* d_in, const int* in_sizes, int n_in,
                              void* d_out, int out_size)
{
    const float* x1 = (const float*)d_in[0];
    const float* x2 = (const float*)d_in[1];
    const int*   ei = (const int*)  d_in[2];
    const float* ew = (const float*)d_in[3];
    const float* Wg = (const float*)d_in[4];
    const float* gb = (const float*)d_in[5];
    const float* pa = (const float*)d_in[6];
    const float* lW = (const float*)d_in[7];
    const float* lb = (const float*)d_in[8];
    float* out = (float*)d_out;

    const int n_nodes = in_sizes[0] / N_IN;        // 100000
    const int n_edges = in_sizes[3];               // 800000
    const int n1      = n_nodes + 1;
    const int nb      = (n1 + 1023) / 1024;        // scan blocks (<=128)

    // ---- CSR build (g_deg is zero: static init at t=0, re-zeroed by scan_add) ----
    hist_kernel<<<(n_edges + 255) / 256, 256>>>(ei, n_edges);
    scan_partial_kernel<<<nb, 1024>>>(n_nodes, n1);
    scan_blk_kernel<<<1, 128>>>(nb);
    scan_add_kernel<<<nb, 1024>>>(n_nodes, n1);
    scatter_kernel<<<(n_edges + 255) / 256, 256>>>(ei, ew, n_edges);

    // ---- prep: wsum/bsum + W split ----
    prep_kernel<<<128, 256>>>(lW, lb, Wg);

    const int gemm_blocks = (n_nodes + 127) / 128;
    const int gath_blocks = (int)(((long long)n_nodes * 32 + 255) / 256);

    // ---- pass 1: gemm(x1) then gather while H half is L2-resident ----
    gemm_wmma_kernel<<<gemm_blocks, 256>>>(x1, n_nodes, 0);
    gather_pass_kernel<<<gath_blocks, 256>>>(gb, pa, out, n_nodes, 0);

    // ---- pass 2 ----
    gemm_wmma_kernel<<<gemm_blocks, 256>>>(x2, n_nodes, n_nodes);
    gather_pass_kernel<<<gath_blocks, 256>>>(gb, pa, out, n_nodes, n_nodes);
}

// round 6
// speedup vs baseline: 1.1458x; 1.1458x over previous
#include <cuda_runtime.h>
#include <cuda_bf16.h>
#include <cuda_fp16.h>
#include <mma.h>
#include <cstdint>

using namespace nvcuda;

#define N_IN   256
#define N_H    128
#define MAX_NODES 100000
#define MAX_EDGES 800000

// ---------------- scratch (allocation-free: __device__ globals) ----------------
// fp16 feature matrix [2N, 128] (+128 pad rows for unguarded partial-tile stores)
__device__ __half g_Hh[(2u * MAX_NODES + 128) * N_H];
__device__ __nv_bfloat16 g_Wh[N_IN * N_H];              // W split hi (bf16)
__device__ __nv_bfloat16 g_Wl[N_IN * N_H];              // W split lo (bf16)
__device__ float g_wsum[N_H];                           // rowsum of lin_W
__device__ float g_bsum;                                // sum of lin_b
// CSR scratch (g_deg zero at t=0 via static init; re-zeroed each run by scan_add)
__device__ int   g_deg[MAX_NODES + 1];
__device__ int   g_rowptr[MAX_NODES + 1];
__device__ int   g_fill[MAX_NODES];
__device__ int   g_blk[128];
__device__ int   g_ecol[MAX_EDGES];
__device__ float g_ewt[MAX_EDGES];

// =======================================================================
//  CSR construction
// =======================================================================
__global__ void hist_kernel(const int* __restrict__ ei, int n_edges)
{
    int i = blockIdx.x * blockDim.x + threadIdx.x;
    if (i < n_edges) atomicAdd(&g_deg[__ldg(ei + i)], 1);
}

__global__ __launch_bounds__(1024) void scan_partial_kernel(int n, int n1)
{
    int tid  = threadIdx.x;
    int gid  = blockIdx.x * 1024 + tid;
    int lane = tid & 31, wid = tid >> 5;
    int v = (gid < n) ? g_deg[gid] : 0;
    int inc = v;
    #pragma unroll
    for (int o = 1; o < 32; o <<= 1) {
        int t = __shfl_up_sync(0xffffffffu, inc, o);
        if (lane >= o) inc += t;
    }
    __shared__ int ws[32];
    if (lane == 31) ws[wid] = inc;
    __syncthreads();
    if (wid == 0) {
        int s = ws[lane];
        #pragma unroll
        for (int o = 1; o < 32; o <<= 1) {
            int t = __shfl_up_sync(0xffffffffu, s, o);
            if (lane >= o) s += t;
        }
        ws[lane] = s;
    }
    __syncthreads();
    int woff = wid ? ws[wid - 1] : 0;
    int excl = woff + inc - v;
    if (gid < n1) g_rowptr[gid] = excl;
    if (tid == 1023) g_blk[blockIdx.x] = woff + inc;
}

// parallel exclusive scan of up to 128 block sums
__global__ __launch_bounds__(128) void scan_blk_kernel(int nb)
{
    int tid = threadIdx.x, lane = tid & 31, wid = tid >> 5;
    int v = (tid < nb) ? g_blk[tid] : 0;
    int inc = v;
    #pragma unroll
    for (int o = 1; o < 32; o <<= 1) {
        int t = __shfl_up_sync(0xffffffffu, inc, o);
        if (lane >= o) inc += t;
    }
    __shared__ int ws[4];
    if (lane == 31) ws[wid] = inc;
    __syncthreads();
    int carry = 0;
    #pragma unroll
    for (int w = 0; w < 4; w++) { if (w < wid) carry += ws[w]; }
    if (tid < nb) g_blk[tid] = carry + inc - v;
}

// add block offsets, publish g_fill, re-zero g_deg for the next replay
__global__ __launch_bounds__(1024) void scan_add_kernel(int n, int n1)
{
    int gid = blockIdx.x * 1024 + threadIdx.x;
    if (gid < n1) {
        int r = g_rowptr[gid] + g_blk[blockIdx.x];
        g_rowptr[gid] = r;
        if (gid < n) g_fill[gid] = r;
        g_deg[gid] = 0;
    }
}

__global__ void scatter_kernel(const int* __restrict__ ei, const float* __restrict__ ew,
                               int n_edges)
{
    int i = blockIdx.x * blockDim.x + threadIdx.x;
    if (i >= n_edges) return;
    int   r = __ldg(ei + i);
    int   c = __ldg(ei + n_edges + i);
    float w = __ldg(ew + i);
    int p = atomicAdd(&g_fill[r], 1);
    g_ecol[p] = c;
    g_ewt[p]  = w;
}

// =======================================================================
//  prep (block 0): wsum / bsum;  all blocks: W bf16 split
// =======================================================================
__global__ __launch_bounds__(256) void prep_kernel(
    const float* __restrict__ linW, const float* __restrict__ linb,
    const float* __restrict__ W)
{
    int gi = blockIdx.x * 256 + threadIdx.x;   // 128*256 = 32768 = N_IN*N_H
    {
        float v = __ldg(W + gi);
        __nv_bfloat16 h = __float2bfloat16(v);
        __nv_bfloat16 l = __float2bfloat16(v - __bfloat162float(h));
        g_Wh[gi] = h;
        g_Wl[gi] = l;
    }
    if (blockIdx.x != 0) return;

    int tid  = threadIdx.x;
    int warp = tid >> 5, lane = tid & 31;
    for (int k = warp; k < N_H; k += 8) {
        float s = 0.f;
        #pragma unroll
        for (int j = lane; j < N_H; j += 32) s += linW[k * N_H + j];
        #pragma unroll
        for (int o = 16; o > 0; o >>= 1) s += __shfl_down_sync(0xffffffffu, s, o);
        if (lane == 0) g_wsum[k] = s;
    }
    __shared__ float sb[256];
    sb[tid] = (tid < N_H) ? linb[tid] : 0.f;
    __syncthreads();
    for (int o = 128; o > 0; o >>= 1) { if (tid < o) sb[tid] += sb[tid + o]; __syncthreads(); }
    if (tid == 0) g_bsum = sb[0];
}

// =======================================================================
//  GEMM: g_Hh = [x1;x2] @ W  via wmma bf16 (3-term split), fp16 output
//  Tile 128x128, K=256 in 4 chunks of 64. 256 threads = 8 warps (2x4).
// =======================================================================
#define A_LD 72   // padded leading dim for smem A (bf16 elements)

__global__ __launch_bounds__(256) void gemm_wmma_kernel(
    const float* __restrict__ x1, const float* __restrict__ x2, int n_nodes)
{
    __shared__ __nv_bfloat16 Ah[128][A_LD];
    __shared__ __nv_bfloat16 Al[128][A_LD];
    __shared__ float stage[8][16 * 16 + 8];   // per-warp epilogue staging

    const int m_tot = 2 * n_nodes;
    const int tid = threadIdx.x;
    const int wid = tid >> 5, lid = tid & 31;
    const int warp_m = wid & 1;       // 0..1 -> 64 rows each
    const int warp_n = wid >> 1;      // 0..3 -> 32 cols each
    const int blockRow = blockIdx.x * 128;

    wmma::fragment<wmma::accumulator, 16, 16, 16, float> acc[4][2];
    #pragma unroll
    for (int mi = 0; mi < 4; mi++)
        #pragma unroll
        for (int ni = 0; ni < 2; ni++)
            wmma::fill_fragment(acc[mi][ni], 0.f);

    for (int ch = 0; ch < 4; ch++) {
        const int k0 = ch * 64;
        // ---- stage A chunk [128 x 64], split into bf16 hi/lo ----
        #pragma unroll
        for (int t = 0; t < 8; t++) {
            int e   = t * 256 + tid;           // 0..2047 float4 slots
            int row = e >> 4;                  // 0..127
            int c4  = e & 15;                  // 0..15
            int mg  = blockRow + row;
            float4 v = make_float4(0.f, 0.f, 0.f, 0.f);
            if (mg < m_tot) {
                const float* src = (mg < n_nodes)
                    ? (x1 + (size_t)mg * N_IN)
                    : (x2 + (size_t)(mg - n_nodes) * N_IN);
                v = *reinterpret_cast<const float4*>(src + k0 + c4 * 4);
            }
            __nv_bfloat16 h0 = __float2bfloat16(v.x), l0 = __float2bfloat16(v.x - __bfloat162float(h0));
            __nv_bfloat16 h1 = __float2bfloat16(v.y), l1 = __float2bfloat16(v.y - __bfloat162float(h1));
            __nv_bfloat16 h2 = __float2bfloat16(v.z), l2 = __float2bfloat16(v.z - __bfloat162float(h2));
            __nv_bfloat16 h3 = __float2bfloat16(v.w), l3 = __float2bfloat16(v.w - __bfloat162float(h3));
            __nv_bfloat16* ph = &Ah[row][c4 * 4];
            __nv_bfloat16* pl = &Al[row][c4 * 4];
            ph[0] = h0; ph[1] = h1; ph[2] = h2; ph[3] = h3;
            pl[0] = l0; pl[1] = l1; pl[2] = l2; pl[3] = l3;
        }
        __syncthreads();

        // ---- MMA over 4 k-steps of 16 ----
        #pragma unroll
        for (int ks = 0; ks < 4; ks++) {
            const int kk = ks * 16;
            wmma::fragment<wmma::matrix_a, 16, 16, 16, __nv_bfloat16, wmma::row_major> ah[4], al[4];
            #pragma unroll
            for (int mi = 0; mi < 4; mi++) {
                int r0 = warp_m * 64 + mi * 16;
                wmma::load_matrix_sync(ah[mi], &Ah[r0][kk], A_LD);
                wmma::load_matrix_sync(al[mi], &Al[r0][kk], A_LD);
            }
            #pragma unroll
            for (int ni = 0; ni < 2; ni++) {
                int c0 = warp_n * 32 + ni * 16;
                wmma::fragment<wmma::matrix_b, 16, 16, 16, __nv_bfloat16, wmma::row_major> bh, bl;
                wmma::load_matrix_sync(bh, g_Wh + (size_t)(k0 + kk) * N_H + c0, N_H);
                wmma::load_matrix_sync(bl, g_Wl + (size_t)(k0 + kk) * N_H + c0, N_H);
                #pragma unroll
                for (int mi = 0; mi < 4; mi++) {
                    wmma::mma_sync(acc[mi][ni], ah[mi], bh, acc[mi][ni]);
                    wmma::mma_sync(acc[mi][ni], ah[mi], bl, acc[mi][ni]);
                    wmma::mma_sync(acc[mi][ni], al[mi], bh, acc[mi][ni]);
                }
            }
        }
        __syncthreads();
    }

    // ---- epilogue: stage per-warp frag -> convert fp16 -> store (pad absorbs) ----
    #pragma unroll
    for (int mi = 0; mi < 4; mi++) {
        #pragma unroll
        for (int ni = 0; ni < 2; ni++) {
            wmma::store_matrix_sync(&stage[wid][0], acc[mi][ni], 16, wmma::mem_row_major);
            __syncwarp();
            // 32 threads: each converts 8 floats (half a 16-col row) -> 16B store
            int r    = lid >> 1;
            int cseg = (lid & 1) * 8;
            float4 f0 = *reinterpret_cast<const float4*>(&stage[wid][r * 16 + cseg]);
            float4 f1 = *reinterpret_cast<const float4*>(&stage[wid][r * 16 + cseg + 4]);
            __half2 q0 = __floats2half2_rn(f0.x, f0.y);
            __half2 q1 = __floats2half2_rn(f0.z, f0.w);
            __half2 q2 = __floats2half2_rn(f1.x, f1.y);
            __half2 q3 = __floats2half2_rn(f1.z, f1.w);
            int gr = blockRow + warp_m * 64 + mi * 16 + r;
            int gc = warp_n * 32 + ni * 16 + cseg;
            uint4 pk;
            pk.x = *reinterpret_cast<uint32_t*>(&q0);
            pk.y = *reinterpret_cast<uint32_t*>(&q1);
            pk.z = *reinterpret_cast<uint32_t*>(&q2);
            pk.w = *reinterpret_cast<uint32_t*>(&q3);
            *reinterpret_cast<uint4*>(g_Hh + (size_t)gr * N_H + gc) = pk;
            __syncwarp();
        }
    }
}

// =======================================================================
//  Fused gather-SpMM + epilogue (both passes per edge): warp per row
//  z[i(+N)] = dot(prelu(sum_e w_e H[c_e(+N)] + bias), wsum) + bsum
// =======================================================================
__global__ __launch_bounds__(256) void gather_final_kernel(
    const float* __restrict__ bias, const float* __restrict__ pa,
    float* __restrict__ out, int n_nodes)
{
    int row  = (blockIdx.x * blockDim.x + threadIdx.x) >> 5;
    int lane = threadIdx.x & 31;
    if (row >= n_nodes) return;

    int s = __ldg(&g_rowptr[row]);
    int e = __ldg(&g_rowptr[row + 1]);

    float4 a1 = make_float4(0.f, 0.f, 0.f, 0.f);
    float4 a2 = make_float4(0.f, 0.f, 0.f, 0.f);

    int j = s;
    for (; j + 1 < e; j += 2) {
        int   c0 = __ldg(&g_ecol[j]),  c1 = __ldg(&g_ecol[j + 1]);
        float w0 = __ldg(&g_ewt[j]),   w1 = __ldg(&g_ewt[j + 1]);
        uint2 p0 = reinterpret_cast<const uint2*>(g_Hh + (size_t)c0 * N_H)[lane];
        uint2 p1 = reinterpret_cast<const uint2*>(g_Hh + (size_t)(c0 + n_nodes) * N_H)[lane];
        uint2 p2 = reinterpret_cast<const uint2*>(g_Hh + (size_t)c1 * N_H)[lane];
        uint2 p3 = reinterpret_cast<const uint2*>(g_Hh + (size_t)(c1 + n_nodes) * N_H)[lane];
        float2 u0 = __half22float2(*reinterpret_cast<__half2*>(&p0.x));
        float2 u1 = __half22float2(*reinterpret_cast<__half2*>(&p0.y));
        float2 v0 = __half22float2(*reinterpret_cast<__half2*>(&p1.x));
        float2 v1 = __half22float2(*reinterpret_cast<__half2*>(&p1.y));
        float2 t0 = __half22float2(*reinterpret_cast<__half2*>(&p2.x));
        float2 t1 = __half22float2(*reinterpret_cast<__half2*>(&p2.y));
        float2 r0 = __half22float2(*reinterpret_cast<__half2*>(&p3.x));
        float2 r1 = __half22float2(*reinterpret_cast<__half2*>(&p3.y));
        a1.x += w0 * u0.x + w1 * t0.x;  a1.y += w0 * u0.y + w1 * t0.y;
        a1.z += w0 * u1.x + w1 * t1.x;  a1.w += w0 * u1.y + w1 * t1.y;
        a2.x += w0 * v0.x + w1 * r0.x;  a2.y += w0 * v0.y + w1 * r0.y;
        a2.z += w0 * v1.x + w1 * r1.x;  a2.w += w0 * v1.y + w1 * r1.y;
    }
    if (j < e) {
        int   c0 = __ldg(&g_ecol[j]);
        float w0 = __ldg(&g_ewt[j]);
        uint2 p0 = reinterpret_cast<const uint2*>(g_Hh + (size_t)c0 * N_H)[lane];
        uint2 p1 = reinterpret_cast<const uint2*>(g_Hh + (size_t)(c0 + n_nodes) * N_H)[lane];
        float2 u0 = __half22float2(*reinterpret_cast<__half2*>(&p0.x));
        float2 u1 = __half22float2(*reinterpret_cast<__half2*>(&p0.y));
        float2 v0 = __half22float2(*reinterpret_cast<__half2*>(&p1.x));
        float2 v1 = __half22float2(*reinterpret_cast<__half2*>(&p1.y));
        a1.x += w0 * u0.x;  a1.y += w0 * u0.y;  a1.z += w0 * u1.x;  a1.w += w0 * u1.y;
        a2.x += w0 * v0.x;  a2.y += w0 * v0.y;  a2.z += w0 * v1.x;  a2.w += w0 * v1.y;
    }

    float  a = __ldg(pa);
    float4 b = __ldg(reinterpret_cast<const float4*>(bias) + lane);
    float4 w = *reinterpret_cast<const float4*>(g_wsum + lane * 4);

    float s1 = 0.f, s2 = 0.f, t;
    t = a1.x + b.x; t = (t >= 0.f) ? t : a * t; s1 += t * w.x;
    t = a1.y + b.y; t = (t >= 0.f) ? t : a * t; s1 += t * w.y;
    t = a1.z + b.z; t = (t >= 0.f) ? t : a * t; s1 += t * w.z;
    t = a1.w + b.w; t = (t >= 0.f) ? t : a * t; s1 += t * w.w;
    t = a2.x + b.x; t = (t >= 0.f) ? t : a * t; s2 += t * w.x;
    t = a2.y + b.y; t = (t >= 0.f) ? t : a * t; s2 += t * w.y;
    t = a2.z + b.z; t = (t >= 0.f) ? t : a * t; s2 += t * w.z;
    t = a2.w + b.w; t = (t >= 0.f) ? t : a * t; s2 += t * w.w;

    #pragma unroll
    for (int o = 16; o > 0; o >>= 1) {
        s1 += __shfl_down_sync(0xffffffffu, s1, o);
        s2 += __shfl_down_sync(0xffffffffu, s2, o);
    }
    if (lane == 0) {
        out[row]           = s1 + g_bsum;
        out[row + n_nodes] = s2 + g_bsum;
    }
}

// =======================================================================
//  launcher
// =======================================================================
extern "C" void kernel_launch(void* const* d_in, const int* in_sizes, int n_in,
                              void* d_out, int out_size)
{
    const float* x1 = (const float*)d_in[0];
    const float* x2 = (const float*)d_in[1];
    const int*   ei = (const int*)  d_in[2];
    const float* ew = (const float*)d_in[3];
    const float* Wg = (const float*)d_in[4];
    const float* gb = (const float*)d_in[5];
    const float* pa = (const float*)d_in[6];
    const float* lW = (const float*)d_in[7];
    const float* lb = (const float*)d_in[8];
    float* out = (float*)d_out;

    const int n_nodes = in_sizes[0] / N_IN;        // 100000
    const int n_edges = in_sizes[3];               // 800000
    const int m_tot   = 2 * n_nodes;
    const int n1      = n_nodes + 1;
    const int nb      = (n1 + 1023) / 1024;        // <=128

    // ---- CSR build ----
    hist_kernel<<<(n_edges + 255) / 256, 256>>>(ei, n_edges);
    scan_partial_kernel<<<nb, 1024>>>(n_nodes, n1);
    scan_blk_kernel<<<1, 128>>>(nb);
    scan_add_kernel<<<nb, 1024>>>(n_nodes, n1);
    scatter_kernel<<<(n_edges + 255) / 256, 256>>>(ei, ew, n_edges);

    // ---- prep: wsum/bsum + W split ----
    prep_kernel<<<128, 256>>>(lW, lb, Wg);

    // ---- GEMM (wmma bf16 3-term, fp16 output) ----
    gemm_wmma_kernel<<<(m_tot + 127) / 128, 256>>>(x1, x2, n_nodes);

    // ---- fused gather + epilogue (both passes) ----
    {
        long long threads = (long long)n_nodes * 32;
        int blocks = (int)((threads + 255) / 256);
        gather_final_kernel<<<blocks, 256>>>(gb, pa, out, n_nodes);
    }
}

// round 8
// speedup vs baseline: 1.1585x; 1.0110x over previous
#include <cuda_runtime.h>
#include <cuda_bf16.h>
#include <cuda_fp16.h>
#include <mma.h>
#include <cstdint>

using namespace nvcuda;

#define N_IN   256
#define N_H    128
#define MAX_NODES 100000
#define MAX_EDGES 800000

// ---------------- scratch (allocation-free: __device__ globals) ----------------
__device__ __half g_Hh[(2u * MAX_NODES + 128) * N_H];   // fp16 features (+pad rows)
__device__ __nv_bfloat16 g_Wh[N_IN * N_H];              // W split hi (bf16)
__device__ __nv_bfloat16 g_Wl[N_IN * N_H];              // W split lo (bf16)
__device__ float g_wsum[N_H];
__device__ float g_bsum;
// CSR scratch (g_deg zero at t=0 via static init; re-zeroed each run by scan_add)
__device__ int   g_deg[MAX_NODES + 1];
__device__ int   g_rowptr[MAX_NODES + 1];
__device__ int   g_fill[MAX_NODES];
__device__ int   g_blk[128];
__device__ int   g_ecol[MAX_EDGES];
__device__ float g_ewt[MAX_EDGES];

// =======================================================================
//  CSR construction
// =======================================================================
__global__ void hist_kernel(const int* __restrict__ ei, int n_edges)
{
    int i = blockIdx.x * blockDim.x + threadIdx.x;
    if (i < n_edges) atomicAdd(&g_deg[__ldg(ei + i)], 1);
}

__global__ __launch_bounds__(1024) void scan_partial_kernel(int n, int n1)
{
    int tid  = threadIdx.x;
    int gid  = blockIdx.x * 1024 + tid;
    int lane = tid & 31, wid = tid >> 5;
    int v = (gid < n) ? g_deg[gid] : 0;
    int inc = v;
    #pragma unroll
    for (int o = 1; o < 32; o <<= 1) {
        int t = __shfl_up_sync(0xffffffffu, inc, o);
        if (lane >= o) inc += t;
    }
    __shared__ int ws[32];
    if (lane == 31) ws[wid] = inc;
    __syncthreads();
    if (wid == 0) {
        int s = ws[lane];
        #pragma unroll
        for (int o = 1; o < 32; o <<= 1) {
            int t = __shfl_up_sync(0xffffffffu, s, o);
            if (lane >= o) s += t;
        }
        ws[lane] = s;
    }
    __syncthreads();
    int woff = wid ? ws[wid - 1] : 0;
    int excl = woff + inc - v;
    if (gid < n1) g_rowptr[gid] = excl;
    if (tid == 1023) g_blk[blockIdx.x] = woff + inc;
}

__global__ __launch_bounds__(128) void scan_blk_kernel(int nb)
{
    int tid = threadIdx.x, lane = tid & 31, wid = tid >> 5;
    int v = (tid < nb) ? g_blk[tid] : 0;
    int inc = v;
    #pragma unroll
    for (int o = 1; o < 32; o <<= 1) {
        int t = __shfl_up_sync(0xffffffffu, inc, o);
        if (lane >= o) inc += t;
    }
    __shared__ int ws[4];
    if (lane == 31) ws[wid] = inc;
    __syncthreads();
    int carry = 0;
    #pragma unroll
    for (int w = 0; w < 4; w++) { if (w < wid) carry += ws[w]; }
    if (tid < nb) g_blk[tid] = carry + inc - v;
}

__global__ __launch_bounds__(1024) void scan_add_kernel(int n, int n1)
{
    int gid = blockIdx.x * 1024 + threadIdx.x;
    if (gid < n1) {
        int r = g_rowptr[gid] + g_blk[blockIdx.x];
        g_rowptr[gid] = r;
        if (gid < n) g_fill[gid] = r;
        g_deg[gid] = 0;
    }
}

__global__ void scatter_kernel(const int* __restrict__ ei, const float* __restrict__ ew,
                               int n_edges)
{
    int i = blockIdx.x * blockDim.x + threadIdx.x;
    if (i >= n_edges) return;
    int   r = __ldg(ei + i);
    int   c = __ldg(ei + n_edges + i);
    float w = __ldg(ew + i);
    int p = atomicAdd(&g_fill[r], 1);
    g_ecol[p] = c;
    g_ewt[p]  = w;
}

// =======================================================================
//  prep (block 0): wsum / bsum;  all blocks: W bf16 split
// =======================================================================
__global__ __launch_bounds__(256) void prep_kernel(
    const float* __restrict__ linW, const float* __restrict__ linb,
    const float* __restrict__ W)
{
    int gi = blockIdx.x * 256 + threadIdx.x;   // 128*256 = 32768 = N_IN*N_H
    {
        float v = __ldg(W + gi);
        __nv_bfloat16 h = __float2bfloat16(v);
        __nv_bfloat16 l = __float2bfloat16(v - __bfloat162float(h));
        g_Wh[gi] = h;
        g_Wl[gi] = l;
    }
    if (blockIdx.x != 0) return;

    int tid  = threadIdx.x;
    int warp = tid >> 5, lane = tid & 31;
    for (int k = warp; k < N_H; k += 8) {
        float s = 0.f;
        #pragma unroll
        for (int j = lane; j < N_H; j += 32) s += linW[k * N_H + j];
        #pragma unroll
        for (int o = 16; o > 0; o >>= 1) s += __shfl_down_sync(0xffffffffu, s, o);
        if (lane == 0) g_wsum[k] = s;
    }
    __shared__ float sb[256];
    sb[tid] = (tid < N_H) ? linb[tid] : 0.f;
    __syncthreads();
    for (int o = 128; o > 0; o >>= 1) { if (tid < o) sb[tid] += sb[tid + o]; __syncthreads(); }
    if (tid == 0) g_bsum = sb[0];
}

// =======================================================================
//  GEMM: g_Hh = [x1;x2] @ W  via wmma bf16 (3-term split), fp16 output
//  Register-prefetch software pipeline over 4 K-chunks of 64.
// =======================================================================
#define A_LD 72

__global__ __launch_bounds__(256) void gemm_wmma_kernel(
    const float* __restrict__ x1, const float* __restrict__ x2, int n_nodes)
{
    __shared__ __nv_bfloat16 Ah[128][A_LD];
    __shared__ __nv_bfloat16 Al[128][A_LD];
    __shared__ float stage[8][16 * 16 + 8];

    const int m_tot = 2 * n_nodes;
    const int tid = threadIdx.x;
    const int wid = tid >> 5, lid = tid & 31;
    const int warp_m = wid & 1;
    const int warp_n = wid >> 1;
    const int blockRow = blockIdx.x * 128;

    wmma::fragment<wmma::accumulator, 16, 16, 16, float> acc[4][2];
    #pragma unroll
    for (int mi = 0; mi < 4; mi++)
        #pragma unroll
        for (int ni = 0; ni < 2; ni++)
            wmma::fill_fragment(acc[mi][ni], 0.f);

    float4 pre[8];

    // prologue: load chunk 0
    #pragma unroll
    for (int t = 0; t < 8; t++) {
        int e   = t * 256 + tid;
        int row = e >> 4, c4 = e & 15;
        int mg  = blockRow + row;
        pre[t] = make_float4(0.f, 0.f, 0.f, 0.f);
        if (mg < m_tot) {
            const float* src = (mg < n_nodes)
                ? (x1 + (size_t)mg * N_IN)
                : (x2 + (size_t)(mg - n_nodes) * N_IN);
            pre[t] = *reinterpret_cast<const float4*>(src + c4 * 4);
        }
    }

    for (int ch = 0; ch < 4; ch++) {
        // ---- convert prefetched regs -> smem hi/lo ----
        #pragma unroll
        for (int t = 0; t < 8; t++) {
            int e   = t * 256 + tid;
            int row = e >> 4, c4 = e & 15;
            float4 v = pre[t];
            __nv_bfloat16 h0 = __float2bfloat16(v.x), l0 = __float2bfloat16(v.x - __bfloat162float(h0));
            __nv_bfloat16 h1 = __float2bfloat16(v.y), l1 = __float2bfloat16(v.y - __bfloat162float(h1));
            __nv_bfloat16 h2 = __float2bfloat16(v.z), l2 = __float2bfloat16(v.z - __bfloat162float(h2));
            __nv_bfloat16 h3 = __float2bfloat16(v.w), l3 = __float2bfloat16(v.w - __bfloat162float(h3));
            __nv_bfloat16* ph = &Ah[row][c4 * 4];
            __nv_bfloat16* pl = &Al[row][c4 * 4];
            ph[0] = h0; ph[1] = h1; ph[2] = h2; ph[3] = h3;
            pl[0] = l0; pl[1] = l1; pl[2] = l2; pl[3] = l3;
        }
        __syncthreads();

        // ---- prefetch next chunk into regs (overlaps with MMA below) ----
        if (ch < 3) {
            const int k0n = (ch + 1) * 64;
            #pragma unroll
            for (int t = 0; t < 8; t++) {
                int e   = t * 256 + tid;
                int row = e >> 4, c4 = e & 15;
                int mg  = blockRow + row;
                pre[t] = make_float4(0.f, 0.f, 0.f, 0.f);
                if (mg < m_tot) {
                    const float* src = (mg < n_nodes)
                        ? (x1 + (size_t)mg * N_IN)
                        : (x2 + (size_t)(mg - n_nodes) * N_IN);
                    pre[t] = *reinterpret_cast<const float4*>(src + k0n + c4 * 4);
                }
            }
        }

        // ---- MMA over 4 k-steps of 16 ----
        const int k0 = ch * 64;
        #pragma unroll
        for (int ks = 0; ks < 4; ks++) {
            const int kk = ks * 16;
            wmma::fragment<wmma::matrix_a, 16, 16, 16, __nv_bfloat16, wmma::row_major> ah[4], al[4];
            #pragma unroll
            for (int mi = 0; mi < 4; mi++) {
                int r0 = warp_m * 64 + mi * 16;
                wmma::load_matrix_sync(ah[mi], &Ah[r0][kk], A_LD);
                wmma::load_matrix_sync(al[mi], &Al[r0][kk], A_LD);
            }
            #pragma unroll
            for (int ni = 0; ni < 2; ni++) {
                int c0 = warp_n * 32 + ni * 16;
                wmma::fragment<wmma::matrix_b, 16, 16, 16, __nv_bfloat16, wmma::row_major> bh, bl;
                wmma::load_matrix_sync(bh, g_Wh + (size_t)(k0 + kk) * N_H + c0, N_H);
                wmma::load_matrix_sync(bl, g_Wl + (size_t)(k0 + kk) * N_H + c0, N_H);
                #pragma unroll
                for (int mi = 0; mi < 4; mi++) {
                    wmma::mma_sync(acc[mi][ni], ah[mi], bh, acc[mi][ni]);
                    wmma::mma_sync(acc[mi][ni], ah[mi], bl, acc[mi][ni]);
                    wmma::mma_sync(acc[mi][ni], al[mi], bh, acc[mi][ni]);
                }
            }
        }
        __syncthreads();
    }

    // ---- epilogue: stage -> fp16 -> store (pad rows absorb overflow) ----
    #pragma unroll
    for (int mi = 0; mi < 4; mi++) {
        #pragma unroll
        for (int ni = 0; ni < 2; ni++) {
            wmma::store_matrix_sync(&stage[wid][0], acc[mi][ni], 16, wmma::mem_row_major);
            __syncwarp();
            int r    = lid >> 1;
            int cseg = (lid & 1) * 8;
            float4 f0 = *reinterpret_cast<const float4*>(&stage[wid][r * 16 + cseg]);
            float4 f1 = *reinterpret_cast<const float4*>(&stage[wid][r * 16 + cseg + 4]);
            __half2 q0 = __floats2half2_rn(f0.x, f0.y);
            __half2 q1 = __floats2half2_rn(f0.z, f0.w);
            __half2 q2 = __floats2half2_rn(f1.x, f1.y);
            __half2 q3 = __floats2half2_rn(f1.z, f1.w);
            int gr = blockRow + warp_m * 64 + mi * 16 + r;
            int gc = warp_n * 32 + ni * 16 + cseg;
            uint4 pk;
            pk.x = *reinterpret_cast<uint32_t*>(&q0);
            pk.y = *reinterpret_cast<uint32_t*>(&q1);
            pk.z = *reinterpret_cast<uint32_t*>(&q2);
            pk.w = *reinterpret_cast<uint32_t*>(&q3);
            *reinterpret_cast<uint4*>(g_Hh + (size_t)gr * N_H + gc) = pk;
            __syncwarp();
        }
    }
}

// =======================================================================
//  Fused gather-SpMM + epilogue (both passes per edge): warp per row
// =======================================================================
__device__ __forceinline__ void acc_h8(float4& acc4, uint2 p, float wgt)
{
    float2 u0 = __half22float2(*reinterpret_cast<__half2*>(&p.x));
    float2 u1 = __half22float2(*reinterpret_cast<__half2*>(&p.y));
    acc4.x += wgt * u0.x;  acc4.y += wgt * u0.y;
    acc4.z += wgt * u1.x;  acc4.w += wgt * u1.y;
}

__global__ __launch_bounds__(256) void gather_final_kernel(
    const float* __restrict__ bias, const float* __restrict__ pa,
    float* __restrict__ out, int n_nodes)
{
    int row  = (blockIdx.x * blockDim.x + threadIdx.x) >> 5;
    int lane = threadIdx.x & 31;
    if (row >= n_nodes) return;

    int s = __ldg(&g_rowptr[row]);
    int e = __ldg(&g_rowptr[row + 1]);

    float4 a1 = make_float4(0.f, 0.f, 0.f, 0.f);
    float4 a2 = make_float4(0.f, 0.f, 0.f, 0.f);

    int j = s;
    for (; j + 3 < e; j += 4) {
        int   c0 = __ldg(&g_ecol[j]),     c1 = __ldg(&g_ecol[j + 1]);
        int   c2 = __ldg(&g_ecol[j + 2]), c3 = __ldg(&g_ecol[j + 3]);
        float w0 = __ldg(&g_ewt[j]),      w1 = __ldg(&g_ewt[j + 1]);
        float w2 = __ldg(&g_ewt[j + 2]),  w3 = __ldg(&g_ewt[j + 3]);
        uint2 pA0 = reinterpret_cast<const uint2*>(g_Hh + (size_t)c0 * N_H)[lane];
        uint2 pB0 = reinterpret_cast<const uint2*>(g_Hh + (size_t)(c0 + n_nodes) * N_H)[lane];
        uint2 pA1 = reinterpret_cast<const uint2*>(g_Hh + (size_t)c1 * N_H)[lane];
        uint2 pB1 = reinterpret_cast<const uint2*>(g_Hh + (size_t)(c1 + n_nodes) * N_H)[lane];
        uint2 pA2 = reinterpret_cast<const uint2*>(g_Hh + (size_t)c2 * N_H)[lane];
        uint2 pB2 = reinterpret_cast<const uint2*>(g_Hh + (size_t)(c2 + n_nodes) * N_H)[lane];
        uint2 pA3 = reinterpret_cast<const uint2*>(g_Hh + (size_t)c3 * N_H)[lane];
        uint2 pB3 = reinterpret_cast<const uint2*>(g_Hh + (size_t)(c3 + n_nodes) * N_H)[lane];
        acc_h8(a1, pA0, w0); acc_h8(a1, pA1, w1); acc_h8(a1, pA2, w2); acc_h8(a1, pA3, w3);
        acc_h8(a2, pB0, w0); acc_h8(a2, pB1, w1); acc_h8(a2, pB2, w2); acc_h8(a2, pB3, w3);
    }
    for (; j < e; j++) {
        int   c0 = __ldg(&g_ecol[j]);
        float w0 = __ldg(&g_ewt[j]);
        uint2 pA0 = reinterpret_cast<const uint2*>(g_Hh + (size_t)c0 * N_H)[lane];
        uint2 pB0 = reinterpret_cast<const uint2*>(g_Hh + (size_t)(c0 + n_nodes) * N_H)[lane];
        acc_h8(a1, pA0, w0);
        acc_h8(a2, pB0, w0);
    }

    float  a = __ldg(pa);
    float4 b = __ldg(reinterpret_cast<const float4*>(bias) + lane);
    float4 w = *reinterpret_cast<const float4*>(g_wsum + lane * 4);

    float s1 = 0.f, s2 = 0.f, t;
    t = a1.x + b.x; t = (t >= 0.f) ? t : a * t; s1 += t * w.x;
    t = a1.y + b.y; t = (t >= 0.f) ? t : a * t; s1 += t * w.y;
    t = a1.z + b.z; t = (t >= 0.f) ? t : a * t; s1 += t * w.z;
    t = a1.w + b.w; t = (t >= 0.f) ? t : a * t; s1 += t * w.w;
    t = a2.x + b.x; t = (t >= 0.f) ? t : a * t; s2 += t * w.x;
    t = a2.y + b.y; t = (t >= 0.f) ? t : a * t; s2 += t * w.y;
    t = a2.z + b.z; t = (t >= 0.f) ? t : a * t; s2 += t * w.z;
    t = a2.w + b.w; t = (t >= 0.f) ? t : a * t; s2 += t * w.w;

    #pragma unroll
    for (int o = 16; o > 0; o >>= 1) {
        s1 += __shfl_down_sync(0xffffffffu, s1, o);
        s2 += __shfl_down_sync(0xffffffffu, s2, o);
    }
    if (lane == 0) {
        out[row]           = s1 + g_bsum;
        out[row + n_nodes] = s2 + g_bsum;
    }
}

// =======================================================================
//  launcher — fork CSR chain onto a side stream, join before gather
// =======================================================================
extern "C" void kernel_launch(void* const* d_in, const int* in_sizes, int n_in,
                              void* d_out, int out_size)
{
    const float* x1 = (const float*)d_in[0];
    const float* x2 = (const float*)d_in[1];
    const int*   ei = (const int*)  d_in[2];
    const float* ew = (const float*)d_in[3];
    const float* Wg = (const float*)d_in[4];
    const float* gb = (const float*)d_in[5];
    const float* pa = (const float*)d_in[6];
    const float* lW = (const float*)d_in[7];
    const float* lb = (const float*)d_in[8];
    float* out = (float*)d_out;

    const int n_nodes = in_sizes[0] / N_IN;        // 100000
    const int n_edges = in_sizes[3];               // 800000
    const int m_tot   = 2 * n_nodes;
    const int n1      = n_nodes + 1;
    const int nb      = (n1 + 1023) / 1024;        // <=128

    static cudaStream_t s_side = nullptr;
    static cudaEvent_t  ev_fork = nullptr, ev_join = nullptr;
    if (s_side == nullptr) {
        cudaStreamCreate(&s_side);
        cudaEventCreateWithFlags(&ev_fork, cudaEventDisableTiming);
        cudaEventCreateWithFlags(&ev_join, cudaEventDisableTiming);
    }

    // fork: side stream inherits current position of the main (capture) stream
    cudaEventRecord(ev_fork, 0);
    cudaStreamWaitEvent(s_side, ev_fork, 0);

    // ---- CSR chain on side stream ----
    hist_kernel<<<(n_edges + 255) / 256, 256, 0, s_side>>>(ei, n_edges);
    scan_partial_kernel<<<nb, 1024, 0, s_side>>>(n_nodes, n1);
    scan_blk_kernel<<<1, 128, 0, s_side>>>(nb);
    scan_add_kernel<<<nb, 1024, 0, s_side>>>(n_nodes, n1);
    scatter_kernel<<<(n_edges + 255) / 256, 256, 0, s_side>>>(ei, ew, n_edges);
    cudaEventRecord(ev_join, s_side);

    // ---- main stream: prep + GEMM (concurrent with CSR) ----
    prep_kernel<<<128, 256>>>(lW, lb, Wg);
    gemm_wmma_kernel<<<(m_tot + 127) / 128, 256>>>(x1, x2, n_nodes);

    // join, then gather
    cudaStreamWaitEvent(0, ev_join, 0);
    {
        long long threads = (long long)n_nodes * 32;
        int blocks = (int)((threads + 255) / 256);
        gather_final_kernel<<<blocks, 256>>>(gb, pa, out, n_nodes);
    }
}

// round 9
// speedup vs baseline: 1.8150x; 1.5667x over previous
#include <cuda_runtime.h>
#include <cuda_fp16.h>
#include <mma.h>
#include <cstdint>

using namespace nvcuda;

#define N_IN   256
#define N_H    128
#define MAX_NODES 100000
#define MAX_EDGES 800000

// ---------------- scratch (allocation-free: __device__ globals) ----------------
__device__ __half g_Hh[(2u * MAX_NODES + 128) * N_H];   // fp16 features (+pad rows)
__device__ __half g_Wf[N_IN * N_H];                     // W in fp16
__device__ float g_wsum[N_H];
__device__ float g_bsum;
// CSR scratch (g_deg zero at t=0 via static init; re-zeroed each run by scan_add)
__device__ int   g_deg[MAX_NODES + 1];
__device__ int   g_rowptr[MAX_NODES + 1];
__device__ int   g_fill[MAX_NODES];
__device__ int   g_blk[128];
__device__ int   g_ecol[MAX_EDGES];
__device__ float g_ewt[MAX_EDGES];

// =======================================================================
//  CSR construction
// =======================================================================
__global__ void hist_kernel(const int* __restrict__ ei, int n_edges)
{
    int i = blockIdx.x * blockDim.x + threadIdx.x;
    if (i < n_edges) atomicAdd(&g_deg[__ldg(ei + i)], 1);
}

__global__ __launch_bounds__(1024) void scan_partial_kernel(int n, int n1)
{
    int tid  = threadIdx.x;
    int gid  = blockIdx.x * 1024 + tid;
    int lane = tid & 31, wid = tid >> 5;
    int v = (gid < n) ? g_deg[gid] : 0;
    int inc = v;
    #pragma unroll
    for (int o = 1; o < 32; o <<= 1) {
        int t = __shfl_up_sync(0xffffffffu, inc, o);
        if (lane >= o) inc += t;
    }
    __shared__ int ws[32];
    if (lane == 31) ws[wid] = inc;
    __syncthreads();
    if (wid == 0) {
        int s = ws[lane];
        #pragma unroll
        for (int o = 1; o < 32; o <<= 1) {
            int t = __shfl_up_sync(0xffffffffu, s, o);
            if (lane >= o) s += t;
        }
        ws[lane] = s;
    }
    __syncthreads();
    int woff = wid ? ws[wid - 1] : 0;
    int excl = woff + inc - v;
    if (gid < n1) g_rowptr[gid] = excl;
    if (tid == 1023) g_blk[blockIdx.x] = woff + inc;
}

__global__ __launch_bounds__(128) void scan_blk_kernel(int nb)
{
    int tid = threadIdx.x, lane = tid & 31, wid = tid >> 5;
    int v = (tid < nb) ? g_blk[tid] : 0;
    int inc = v;
    #pragma unroll
    for (int o = 1; o < 32; o <<= 1) {
        int t = __shfl_up_sync(0xffffffffu, inc, o);
        if (lane >= o) inc += t;
    }
    __shared__ int ws[4];
    if (lane == 31) ws[wid] = inc;
    __syncthreads();
    int carry = 0;
    #pragma unroll
    for (int w = 0; w < 4; w++) { if (w < wid) carry += ws[w]; }
    if (tid < nb) g_blk[tid] = carry + inc - v;
}

__global__ __launch_bounds__(1024) void scan_add_kernel(int n, int n1)
{
    int gid = blockIdx.x * 1024 + threadIdx.x;
    if (gid < n1) {
        int r = g_rowptr[gid] + g_blk[blockIdx.x];
        g_rowptr[gid] = r;
        if (gid < n) g_fill[gid] = r;
        g_deg[gid] = 0;
    }
}

__global__ void scatter_kernel(const int* __restrict__ ei, const float* __restrict__ ew,
                               int n_edges)
{
    int i = blockIdx.x * blockDim.x + threadIdx.x;
    if (i >= n_edges) return;
    int   r = __ldg(ei + i);
    int   c = __ldg(ei + n_edges + i);
    float w = __ldg(ew + i);
    int p = atomicAdd(&g_fill[r], 1);
    g_ecol[p] = c;
    g_ewt[p]  = w;
}

// =======================================================================
//  prep (block 0): wsum / bsum;  all blocks: W -> fp16
// =======================================================================
__global__ __launch_bounds__(256) void prep_kernel(
    const float* __restrict__ linW, const float* __restrict__ linb,
    const float* __restrict__ W)
{
    int gi = blockIdx.x * 256 + threadIdx.x;   // 128*256 = 32768 = N_IN*N_H
    g_Wf[gi] = __float2half_rn(__ldg(W + gi));
    if (blockIdx.x != 0) return;

    int tid  = threadIdx.x;
    int warp = tid >> 5, lane = tid & 31;
    for (int k = warp; k < N_H; k += 8) {
        float s = 0.f;
        #pragma unroll
        for (int j = lane; j < N_H; j += 32) s += linW[k * N_H + j];
        #pragma unroll
        for (int o = 16; o > 0; o >>= 1) s += __shfl_down_sync(0xffffffffu, s, o);
        if (lane == 0) g_wsum[k] = s;
    }
    __shared__ float sb[256];
    sb[tid] = (tid < N_H) ? linb[tid] : 0.f;
    __syncthreads();
    for (int o = 128; o > 0; o >>= 1) { if (tid < o) sb[tid] += sb[tid + o]; __syncthreads(); }
    if (tid == 0) g_bsum = sb[0];
}

// =======================================================================
//  GEMM: g_Hh = fp16([x1;x2]) @ fp16(W), fp32 accumulate, fp16 output.
//  Tile 128x128, K=256 in 4 chunks of 64; register-prefetch pipeline.
// =======================================================================
#define A_LD 72

__global__ __launch_bounds__(256) void gemm_wmma_kernel(
    const float* __restrict__ x1, const float* __restrict__ x2, int n_nodes)
{
    __shared__ __half Ah[128][A_LD];
    __shared__ float stage[8][16 * 16 + 8];

    const int m_tot = 2 * n_nodes;
    const int tid = threadIdx.x;
    const int wid = tid >> 5, lid = tid & 31;
    const int warp_m = wid & 1;
    const int warp_n = wid >> 1;
    const int blockRow = blockIdx.x * 128;

    wmma::fragment<wmma::accumulator, 16, 16, 16, float> acc[4][2];
    #pragma unroll
    for (int mi = 0; mi < 4; mi++)
        #pragma unroll
        for (int ni = 0; ni < 2; ni++)
            wmma::fill_fragment(acc[mi][ni], 0.f);

    float4 pre[8];

    // prologue: load chunk 0
    #pragma unroll
    for (int t = 0; t < 8; t++) {
        int e   = t * 256 + tid;
        int row = e >> 4, c4 = e & 15;
        int mg  = blockRow + row;
        pre[t] = make_float4(0.f, 0.f, 0.f, 0.f);
        if (mg < m_tot) {
            const float* src = (mg < n_nodes)
                ? (x1 + (size_t)mg * N_IN)
                : (x2 + (size_t)(mg - n_nodes) * N_IN);
            pre[t] = *reinterpret_cast<const float4*>(src + c4 * 4);
        }
    }

    for (int ch = 0; ch < 4; ch++) {
        // ---- convert prefetched regs -> smem fp16 ----
        #pragma unroll
        for (int t = 0; t < 8; t++) {
            int e   = t * 256 + tid;
            int row = e >> 4, c4 = e & 15;
            float4 v = pre[t];
            __half2 h01 = __floats2half2_rn(v.x, v.y);
            __half2 h23 = __floats2half2_rn(v.z, v.w);
            uint2 pk;
            pk.x = *reinterpret_cast<uint32_t*>(&h01);
            pk.y = *reinterpret_cast<uint32_t*>(&h23);
            *reinterpret_cast<uint2*>(&Ah[row][c4 * 4]) = pk;
        }
        __syncthreads();

        // ---- prefetch next chunk (overlaps with MMA below) ----
        if (ch < 3) {
            const int k0n = (ch + 1) * 64;
            #pragma unroll
            for (int t = 0; t < 8; t++) {
                int e   = t * 256 + tid;
                int row = e >> 4, c4 = e & 15;
                int mg  = blockRow + row;
                pre[t] = make_float4(0.f, 0.f, 0.f, 0.f);
                if (mg < m_tot) {
                    const float* src = (mg < n_nodes)
                        ? (x1 + (size_t)mg * N_IN)
                        : (x2 + (size_t)(mg - n_nodes) * N_IN);
                    pre[t] = *reinterpret_cast<const float4*>(src + k0n + c4 * 4);
                }
            }
        }

        // ---- MMA over 4 k-steps of 16 ----
        const int k0 = ch * 64;
        #pragma unroll
        for (int ks = 0; ks < 4; ks++) {
            const int kk = ks * 16;
            wmma::fragment<wmma::matrix_a, 16, 16, 16, __half, wmma::row_major> af[4];
            #pragma unroll
            for (int mi = 0; mi < 4; mi++) {
                int r0 = warp_m * 64 + mi * 16;
                wmma::load_matrix_sync(af[mi], &Ah[r0][kk], A_LD);
            }
            #pragma unroll
            for (int ni = 0; ni < 2; ni++) {
                int c0 = warp_n * 32 + ni * 16;
                wmma::fragment<wmma::matrix_b, 16, 16, 16, __half, wmma::row_major> bf;
                wmma::load_matrix_sync(bf, g_Wf + (size_t)(k0 + kk) * N_H + c0, N_H);
                #pragma unroll
                for (int mi = 0; mi < 4; mi++)
                    wmma::mma_sync(acc[mi][ni], af[mi], bf, acc[mi][ni]);
            }
        }
        __syncthreads();
    }

    // ---- epilogue: stage -> fp16 -> store (pad rows absorb overflow) ----
    #pragma unroll
    for (int mi = 0; mi < 4; mi++) {
        #pragma unroll
        for (int ni = 0; ni < 2; ni++) {
            wmma::store_matrix_sync(&stage[wid][0], acc[mi][ni], 16, wmma::mem_row_major);
            __syncwarp();
            int r    = lid >> 1;
            int cseg = (lid & 1) * 8;
            float4 f0 = *reinterpret_cast<const float4*>(&stage[wid][r * 16 + cseg]);
            float4 f1 = *reinterpret_cast<const float4*>(&stage[wid][r * 16 + cseg + 4]);
            __half2 q0 = __floats2half2_rn(f0.x, f0.y);
            __half2 q1 = __floats2half2_rn(f0.z, f0.w);
            __half2 q2 = __floats2half2_rn(f1.x, f1.y);
            __half2 q3 = __floats2half2_rn(f1.z, f1.w);
            int gr = blockRow + warp_m * 64 + mi * 16 + r;
            int gc = warp_n * 32 + ni * 16 + cseg;
            uint4 pk;
            pk.x = *reinterpret_cast<uint32_t*>(&q0);
            pk.y = *reinterpret_cast<uint32_t*>(&q1);
            pk.z = *reinterpret_cast<uint32_t*>(&q2);
            pk.w = *reinterpret_cast<uint32_t*>(&q3);
            *reinterpret_cast<uint4*>(g_Hh + (size_t)gr * N_H + gc) = pk;
            __syncwarp();
        }
    }
}

// =======================================================================
//  Fused gather-SpMM + epilogue (both passes per edge): warp per row
// =======================================================================
__device__ __forceinline__ void acc_h8(float4& acc4, uint2 p, float wgt)
{
    float2 u0 = __half22float2(*reinterpret_cast<__half2*>(&p.x));
    float2 u1 = __half22float2(*reinterpret_cast<__half2*>(&p.y));
    acc4.x += wgt * u0.x;  acc4.y += wgt * u0.y;
    acc4.z += wgt * u1.x;  acc4.w += wgt * u1.y;
}

__global__ __launch_bounds__(256) void gather_final_kernel(
    const float* __restrict__ bias, const float* __restrict__ pa,
    float* __restrict__ out, int n_nodes)
{
    int row  = (blockIdx.x * blockDim.x + threadIdx.x) >> 5;
    int lane = threadIdx.x & 31;
    if (row >= n_nodes) return;

    int s = __ldg(&g_rowptr[row]);
    int e = __ldg(&g_rowptr[row + 1]);

    float4 a1 = make_float4(0.f, 0.f, 0.f, 0.f);
    float4 a2 = make_float4(0.f, 0.f, 0.f, 0.f);

    int j = s;
    for (; j + 3 < e; j += 4) {
        int   c0 = __ldg(&g_ecol[j]),     c1 = __ldg(&g_ecol[j + 1]);
        int   c2 = __ldg(&g_ecol[j + 2]), c3 = __ldg(&g_ecol[j + 3]);
        float w0 = __ldg(&g_ewt[j]),      w1 = __ldg(&g_ewt[j + 1]);
        float w2 = __ldg(&g_ewt[j + 2]),  w3 = __ldg(&g_ewt[j + 3]);
        uint2 pA0 = reinterpret_cast<const uint2*>(g_Hh + (size_t)c0 * N_H)[lane];
        uint2 pB0 = reinterpret_cast<const uint2*>(g_Hh + (size_t)(c0 + n_nodes) * N_H)[lane];
        uint2 pA1 = reinterpret_cast<const uint2*>(g_Hh + (size_t)c1 * N_H)[lane];
        uint2 pB1 = reinterpret_cast<const uint2*>(g_Hh + (size_t)(c1 + n_nodes) * N_H)[lane];
        uint2 pA2 = reinterpret_cast<const uint2*>(g_Hh + (size_t)c2 * N_H)[lane];
        uint2 pB2 = reinterpret_cast<const uint2*>(g_Hh + (size_t)(c2 + n_nodes) * N_H)[lane];
        uint2 pA3 = reinterpret_cast<const uint2*>(g_Hh + (size_t)c3 * N_H)[lane];
        uint2 pB3 = reinterpret_cast<const uint2*>(g_Hh + (size_t)(c3 + n_nodes) * N_H)[lane];
        acc_h8(a1, pA0, w0); acc_h8(a1, pA1, w1); acc_h8(a1, pA2, w2); acc_h8(a1, pA3, w3);
        acc_h8(a2, pB0, w0); acc_h8(a2, pB1, w1); acc_h8(a2, pB2, w2); acc_h8(a2, pB3, w3);
    }
    for (; j < e; j++) {
        int   c0 = __ldg(&g_ecol[j]);
        float w0 = __ldg(&g_ewt[j]);
        uint2 pA0 = reinterpret_cast<const uint2*>(g_Hh + (size_t)c0 * N_H)[lane];
        uint2 pB0 = reinterpret_cast<const uint2*>(g_Hh + (size_t)(c0 + n_nodes) * N_H)[lane];
        acc_h8(a1, pA0, w0);
        acc_h8(a2, pB0, w0);
    }

    float  a = __ldg(pa);
    float4 b = __ldg(reinterpret_cast<const float4*>(bias) + lane);
    float4 w = *reinterpret_cast<const float4*>(g_wsum + lane * 4);

    float s1 = 0.f, s2 = 0.f, t;
    t = a1.x + b.x; t = (t >= 0.f) ? t : a * t; s1 += t * w.x;
    t = a1.y + b.y; t = (t >= 0.f) ? t : a * t; s1 += t * w.y;
    t = a1.z + b.z; t = (t >= 0.f) ? t : a * t; s1 += t * w.z;
    t = a1.w + b.w; t = (t >= 0.f) ? t : a * t; s1 += t * w.w;
    t = a2.x + b.x; t = (t >= 0.f) ? t : a * t; s2 += t * w.x;
    t = a2.y + b.y; t = (t >= 0.f) ? t : a * t; s2 += t * w.y;
    t = a2.z + b.z; t = (t >= 0.f) ? t : a * t; s2 += t * w.z;
    t = a2.w + b.w; t = (t >= 0.f) ? t : a * t; s2 += t * w.w;

    #pragma unroll
    for (int o = 16; o > 0; o >>= 1) {
        s1 += __shfl_down_sync(0xffffffffu, s1, o);
        s2 += __shfl_down_sync(0xffffffffu, s2, o);
    }
    if (lane == 0) {
        out[row]           = s1 + g_bsum;
        out[row + n_nodes] = s2 + g_bsum;
    }
}

// =======================================================================
//  launcher — fork CSR chain onto a side stream, join before gather
// =======================================================================
extern "C" void kernel_launch(void* const* d_in, const int* in_sizes, int n_in,
                              void* d_out, int out_size)
{
    const float* x1 = (const float*)d_in[0];
    const float* x2 = (const float*)d_in[1];
    const int*   ei = (const int*)  d_in[2];
    const float* ew = (const float*)d_in[3];
    const float* Wg = (const float*)d_in[4];
    const float* gb = (const float*)d_in[5];
    const float* pa = (const float*)d_in[6];
    const float* lW = (const float*)d_in[7];
    const float* lb = (const float*)d_in[8];
    float* out = (float*)d_out;

    const int n_nodes = in_sizes[0] / N_IN;        // 100000
    const int n_edges = in_sizes[3];               // 800000
    const int m_tot   = 2 * n_nodes;
    const int n1      = n_nodes + 1;
    const int nb      = (n1 + 1023) / 1024;        // <=128

    static cudaStream_t s_side = nullptr;
    static cudaEvent_t  ev_fork = nullptr, ev_join = nullptr;
    if (s_side == nullptr) {
        cudaStreamCreate(&s_side);
        cudaEventCreateWithFlags(&ev_fork, cudaEventDisableTiming);
        cudaEventCreateWithFlags(&ev_join, cudaEventDisableTiming);
    }

    cudaEventRecord(ev_fork, 0);
    cudaStreamWaitEvent(s_side, ev_fork, 0);

    // ---- CSR chain on side stream ----
    hist_kernel<<<(n_edges + 255) / 256, 256, 0, s_side>>>(ei, n_edges);
    scan_partial_kernel<<<nb, 1024, 0, s_side>>>(n_nodes, n1);
    scan_blk_kernel<<<1, 128, 0, s_side>>>(nb);
    scan_add_kernel<<<nb, 1024, 0, s_side>>>(n_nodes, n1);
    scatter_kernel<<<(n_edges + 255) / 256, 256, 0, s_side>>>(ei, ew, n_edges);
    cudaEventRecord(ev_join, s_side);

    // ---- main stream: prep + GEMM (concurrent with CSR) ----
    prep_kernel<<<128, 256>>>(lW, lb, Wg);
    gemm_wmma_kernel<<<(m_tot + 127) / 128, 256>>>(x1, x2, n_nodes);

    // join, then gather
    cudaStreamWaitEvent(0, ev_join, 0);
    {
        long long threads = (long long)n_nodes * 32;
        int blocks = (int)((threads + 255) / 256);
        gather_final_kernel<<<blocks, 256>>>(gb, pa, out, n_nodes);
    }
}